// round 10
// baseline (speedup 1.0000x reference)
#include <cuda_runtime.h>
#include <cuda_fp16.h>
#include <math.h>
#include <stdint.h>

// ---------------- problem constants ----------------
#define BB 8
#define NN 8192
#define CC 512
#define KK 64
#define DD 128
#define TOKN 256
#define MTOT (BB*NN)          // 65536
#define HDIM 1024
#define OUTW (TOKN + DD*KK)   // 8448

// ---------------- scratch (device globals) ----------------
__device__ __half g_Xh[(size_t)MTOT * CC];          // fp16 copy of x
__device__ __half g_Hh[(size_t)MTOT * HDIM];        // layer-1 activations (fp16)
__device__ __half g_localh[(size_t)MTOT * DD];      // local features (fp16)
__device__ float g_E[(size_t)BB * 65 * NN];         // exp(scores) [b,65,n]
__device__ float g_eu[BB * 65];
__device__ float g_ev[BB * NN];
__device__ float g_gp[BB * 32 * CC];
__device__ float g_gt[BB * TOKN];
__device__ float g_aggp[(size_t)BB * 32 * DD * KK]; // partials, [k][d] order per chunk
__device__ float g_agg[BB * DD * KK];
__device__ __half g_W1h[1024 * 512];                // [cW1;sW1] fp16
__device__ __half g_W2h[192 * 512];                 // [cW2;sW2] fp16
__device__ float g_b1r[1024];
__device__ float g_b2r[192];

// ---------------- helpers ----------------
__device__ __forceinline__ float compute_p(float w) {
    float sp = (w > 20.f) ? w : log1pf(expf(w));
    return fminf(sp + 1e-3f, 10.0f);
}
__device__ __forceinline__ uint32_t smem_u32(const void* p) {
    uint32_t a;
    asm("{ .reg .u64 t; cvta.to.shared.u64 t, %1; cvt.u32.u64 %0, t; }" : "=r"(a) : "l"(p));
    return a;
}
__device__ __forceinline__ void cp16(uint32_t dst, const void* src) {
    asm volatile("cp.async.cg.shared.global [%0], [%1], 16;" :: "r"(dst), "l"(src));
}
__device__ __forceinline__ void cp_commit() {
    asm volatile("cp.async.commit_group;" ::: "memory");
}
template<int N> __device__ __forceinline__ void cp_wait() {
    asm volatile("cp.async.wait_group %0;" :: "n"(N) : "memory");
}
__device__ __forceinline__ void mma_f16(float* d, const uint32_t* a, const uint32_t* b) {
    asm volatile(
        "mma.sync.aligned.m16n8k16.row.col.f32.f16.f16.f32 "
        "{%0,%1,%2,%3}, {%4,%5,%6,%7}, {%8,%9}, {%0,%1,%2,%3};\n"
        : "+f"(d[0]), "+f"(d[1]), "+f"(d[2]), "+f"(d[3])
        : "r"(a[0]), "r"(a[1]), "r"(a[2]), "r"(a[3]), "r"(b[0]), "r"(b[1]));
}
__device__ __forceinline__ void ldsm_x4(uint32_t& r0, uint32_t& r1, uint32_t& r2, uint32_t& r3,
                                        uint32_t addr) {
    asm volatile("ldmatrix.sync.aligned.m8n8.x4.shared.b16 {%0,%1,%2,%3}, [%4];"
                 : "=r"(r0), "=r"(r1), "=r"(r2), "=r"(r3) : "r"(addr));
}
__device__ __forceinline__ void ldsm_x2_trans(uint32_t& r0, uint32_t& r1, uint32_t addr) {
    asm volatile("ldmatrix.sync.aligned.m8n8.x2.trans.shared.b16 {%0,%1}, [%2];"
                 : "=r"(r0), "=r"(r1) : "r"(addr));
}

// ---------------- prep: weights -> fp16 concat, ev=1, dust row of E ----------------
__global__ void k_prep(const float* __restrict__ cW1, const float* __restrict__ cb1,
                       const float* __restrict__ sW1, const float* __restrict__ sb1,
                       const float* __restrict__ cW2, const float* __restrict__ cb2,
                       const float* __restrict__ sW2, const float* __restrict__ sb2,
                       const float* __restrict__ dust) {
    int i = blockIdx.x * 256 + threadIdx.x;   // 2432*256 = 622592
    if (i < 1024 * 512) {
        g_W1h[i] = __float2half_rn(i < 512 * 512 ? cW1[i] : sW1[i - 512 * 512]);
    } else {
        int j = i - 1024 * 512;               // < 98304
        if (j < 128 * 512) g_W2h[j] = __float2half_rn(cW2[j]);
        else               g_W2h[j] = __float2half_rn(sW2[j - 128 * 512]);
    }
    if (i < 1024) g_b1r[i] = (i < 512) ? cb1[i] : sb1[i - 512];
    else if (i < 1024 + 192) { int j = i - 1024; g_b2r[j] = (j < 128) ? cb2[j] : sb2[j - 128]; }
    if (i < 65536) {
        g_ev[i] = 1.f;
        int b = i >> 13, n = i & (NN - 1);
        g_E[((size_t)b * 65 + 64) * NN + n] = expf(dust[0]);
    }
}

// ---------------- GeM pooling (+ fp16 conversion of x, fused) ----------------
__global__ void k_gem_part(const float* __restrict__ x, const float* __restrict__ gem_w) {
    int b = blockIdx.y, part = blockIdx.x, c = threadIdx.x;
    float p = compute_p(gem_w[0]);
    bool cube = fabsf(p - 3.0f) < 1e-5f;
    size_t base = ((size_t)b * NN + part * 256) * CC + c;
    const float* xp = x + base;
    __half* xh = g_Xh + base;
    float s = 0.f;
    if (cube) {
        #pragma unroll 4
        for (int n = 0; n < 256; n++) {
            float xv = xp[(size_t)n * CC];
            xh[(size_t)n * CC] = __float2half_rn(xv);
            float v = fmaxf(xv, 1e-6f);
            s += v * v * v;
        }
    } else {
        for (int n = 0; n < 256; n++) {
            float xv = xp[(size_t)n * CC];
            xh[(size_t)n * CC] = __float2half_rn(xv);
            float v = fmaxf(xv, 1e-6f);
            s += __powf(v, p);
        }
    }
    g_gp[(b * 32 + part) * CC + c] = s;
}

// ---------------- head: gem_fin + token MLP (both layers), one block per b ----------------
__global__ __launch_bounds__(512) void k_head(const float* __restrict__ gem_w,
                                              const float* __restrict__ tW1, const float* __restrict__ tb1,
                                              const float* __restrict__ tW2, const float* __restrict__ tb2) {
    int b = blockIdx.x, tid = threadIdx.x;     // 512 threads
    int warp = tid >> 5, lane = tid & 31;
    __shared__ float gs[512], hs[512];
    {
        float s = 0.f;
        #pragma unroll
        for (int i = 0; i < 32; i++) s += g_gp[(b * 32 + i) * CC + tid];
        float p = compute_p(gem_w[0]);
        float mean = s * (1.0f / (float)NN);
        float g = powf(mean, 1.0f / p);
        if (!isfinite(g)) g = 0.f;
        gs[tid] = g;
    }
    __syncthreads();
    for (int t = warp; t < 512; t += 16) {
        const float* w = tW1 + (size_t)t * CC;
        float s = 0.f;
        #pragma unroll
        for (int c = lane; c < CC; c += 32) s = fmaf(gs[c], w[c], s);
        #pragma unroll
        for (int o = 16; o > 0; o >>= 1) s += __shfl_xor_sync(0xffffffffu, s, o);
        if (lane == 0) hs[t] = fmaxf(s + tb1[t], 0.f);
    }
    __syncthreads();
    for (int t = warp; t < 256; t += 16) {
        const float* w = tW2 + (size_t)t * 512;
        float s = 0.f;
        #pragma unroll
        for (int c = lane; c < 512; c += 32) s = fmaf(hs[c], w[c], s);
        #pragma unroll
        for (int o = 16; o > 0; o >>= 1) s += __shfl_xor_sync(0xffffffffu, s, o);
        if (lane == 0) g_gt[b * TOKN + t] = s + tb2[t];
    }
}

// ================ fp16 mma.sync GEMM, cp.async pipeline + ldmatrix fragments ================
// BM=128, BN template, BK=32 halfs, 4 stages, 256 threads, 2 CTAs/SM.
// MODE 0: Hh = relu(Xh @ W1h^T + b1)        (BN=128)
// MODE 1: localh = Hh[:, :512] @ cW2h^T + b (BN=128)
// MODE 2: E = exp(Hh[:, 512:] @ sW2h^T + b) (BN=64, transposed store)
template<int BN, int MODE>
__global__ __launch_bounds__(256, 2) void k_mm() {
    constexpr int STAGES = 4;
    constexpr int NKB = 16;
    constexpr int ROWS = 128 + BN;
    constexpr int STRIDE_H = 40;               // halfs per row
    constexpr int NWN = BN / 32;
    constexpr int NWM = 8 / NWN;
    constexpr int MI = (128 / NWM) / 16;

    extern __shared__ __align__(16) __half smem[];
    uint32_t sbase = smem_u32(smem);

    int tid = threadIdx.x;
    int warpid = tid >> 5, lane = tid & 31;
    int g = lane >> 2, l4 = lane & 3;
    int wm = (warpid / NWN) * (128 / NWM);
    int wn = (warpid % NWN) * 32;
    int m0 = blockIdx.y * 128;
    int col0 = blockIdx.x * BN;

    const __half* Ap; int lda; const __half* Bw; const float* bias;
    if (MODE == 0)      { Ap = g_Xh;        lda = 512;  Bw = g_W1h;             bias = g_b1r; }
    else if (MODE == 1) { Ap = g_Hh;        lda = 1024; Bw = g_W2h;             bias = g_b2r; }
    else                { Ap = g_Hh + 512;  lda = 1024; Bw = g_W2h + 128 * 512; bias = g_b2r + 128; }

    float acc[MI][4][4];
    #pragma unroll
    for (int i = 0; i < MI; i++)
        #pragma unroll
        for (int j = 0; j < 4; j++)
            #pragma unroll
            for (int r = 0; r < 4; r++) acc[i][j][r] = 0.f;

    // per-lane ldmatrix byte offsets (within a stage)
    int lrowA = (lane & 7) + ((lane >> 3) & 1) * 8;   // 16 rows
    int lcol = (lane >> 4) * 8;                       // halfs
    uint32_t offA[MI];
    #pragma unroll
    for (int i = 0; i < MI; i++)
        offA[i] = (uint32_t)((wm + i * 16 + lrowA) * STRIDE_H + lcol) * 2;
    uint32_t offB[2];
    #pragma unroll
    for (int jp = 0; jp < 2; jp++)
        offB[jp] = (uint32_t)((128 + wn + jp * 16 + (lane & 15)) * STRIDE_H + lcol) * 2;

    auto load_stage = [&](int kb, int st) {
        uint32_t base = sbase + (uint32_t)st * ROWS * STRIDE_H * 2;
        int ko = kb * 32;
        constexpr int CHUNKS = ROWS * 4;
        #pragma unroll
        for (int t = 0; t < CHUNKS / 256; t++) {
            int c = tid + t * 256;
            int row = c >> 2, q = c & 3;
            const __half* src = (row < 128)
                ? (Ap + (size_t)(m0 + row) * lda + ko + q * 8)
                : (Bw + (size_t)(col0 + row - 128) * 512 + ko + q * 8);
            cp16(base + (uint32_t)(row * STRIDE_H + q * 8) * 2, src);
        }
    };

    #pragma unroll
    for (int s = 0; s < STAGES - 1; s++) { load_stage(s, s); cp_commit(); }

    for (int kb = 0; kb < NKB; kb++) {
        cp_wait<STAGES - 2>();
        __syncthreads();
        if (kb + STAGES - 1 < NKB) load_stage(kb + STAGES - 1, (kb + STAGES - 1) % STAGES);
        cp_commit();

        uint32_t stageB = sbase + (uint32_t)(kb % STAGES) * ROWS * STRIDE_H * 2;
        #pragma unroll
        for (int kk = 0; kk < 2; kk++) {
            uint32_t kboff = stageB + kk * 32;          // 16 halfs = 32 B
            uint32_t a[MI][4], b[4][2];
            #pragma unroll
            for (int i = 0; i < MI; i++)
                ldsm_x4(a[i][0], a[i][1], a[i][2], a[i][3], kboff + offA[i]);
            #pragma unroll
            for (int jp = 0; jp < 2; jp++)
                ldsm_x4(b[2 * jp][0], b[2 * jp + 1][0], b[2 * jp][1], b[2 * jp + 1][1],
                        kboff + offB[jp]);
            #pragma unroll
            for (int i = 0; i < MI; i++)
                #pragma unroll
                for (int j = 0; j < 4; j++)
                    mma_f16(acc[i][j], a[i], b[j]);
        }
    }

    // ---- epilogue ----
    #pragma unroll
    for (int i = 0; i < MI; i++) {
        #pragma unroll
        for (int j = 0; j < 4; j++) {
            int col = wn + j * 8 + l4 * 2;
            float b0 = bias[col0 + col], b1 = bias[col0 + col + 1];
            int r0 = m0 + wm + i * 16 + g;
            if (MODE == 0) {
                __half2 v0 = __floats2half2_rn(fmaxf(acc[i][j][0] + b0, 0.f),
                                               fmaxf(acc[i][j][1] + b1, 0.f));
                __half2 v1 = __floats2half2_rn(fmaxf(acc[i][j][2] + b0, 0.f),
                                               fmaxf(acc[i][j][3] + b1, 0.f));
                *(__half2*)&g_Hh[(size_t)r0 * HDIM + col0 + col] = v0;
                *(__half2*)&g_Hh[(size_t)(r0 + 8) * HDIM + col0 + col] = v1;
            } else if (MODE == 1) {
                __half2 v0 = __floats2half2_rn(acc[i][j][0] + b0, acc[i][j][1] + b1);
                __half2 v1 = __floats2half2_rn(acc[i][j][2] + b0, acc[i][j][3] + b1);
                *(__half2*)&g_localh[(size_t)r0 * DD + col0 + col] = v0;
                *(__half2*)&g_localh[(size_t)(r0 + 8) * DD + col0 + col] = v1;
            } else {
                int b0i = r0 >> 13, n0i = r0 & (NN - 1);
                int b1i = (r0 + 8) >> 13, n1i = (r0 + 8) & (NN - 1);
                int kc = col0 + col;
                g_E[((size_t)b0i * 65 + kc + 0) * NN + n0i] = expf(acc[i][j][0] + b0);
                g_E[((size_t)b0i * 65 + kc + 1) * NN + n0i] = expf(acc[i][j][1] + b1);
                g_E[((size_t)b1i * 65 + kc + 0) * NN + n1i] = expf(acc[i][j][2] + b0);
                g_E[((size_t)b1i * 65 + kc + 1) * NN + n1i] = expf(acc[i][j][3] + b1);
            }
        }
    }
}

// ---------------- linear-domain Sinkhorn ----------------
__global__ void k_row() {                      // grid (65, 8), 256 thr
    int m = blockIdx.x, b = blockIdx.y, tid = threadIdx.x;
    const float* row = &g_E[((size_t)b * 65 + m) * NN];
    const float* ev = &g_ev[b * NN];
    float s = 0.f;
    for (int n = tid; n < NN; n += 256) s = fmaf(row[n], ev[n], s);
    __shared__ float red[256];
    red[tid] = s;
    __syncthreads();
    #pragma unroll
    for (int o = 128; o > 0; o >>= 1) {
        if (tid < o) red[tid] += red[tid + o];
        __syncthreads();
    }
    if (tid == 0) {
        float a = (m == 64) ? (8128.f / 8256.f) : (1.f / 8256.f);
        g_eu[b * 65 + m] = a / red[0];
    }
}

__global__ void k_col() {                      // grid (32, 8), 256 thr
    int b = blockIdx.y;
    int n = blockIdx.x * 256 + threadIdx.x;
    __shared__ float us[65];
    if (threadIdx.x < 65) us[threadIdx.x] = g_eu[b * 65 + threadIdx.x];
    __syncthreads();
    const float* col = &g_E[(size_t)b * 65 * NN + n];
    float s = 0.f;
    #pragma unroll
    for (int m = 0; m < 65; m++) s = fmaf(col[(size_t)m * NN], us[m], s);
    g_ev[b * NN + n] = (1.f / 8256.f) / s;
}

// ---------------- aggregation via fp16 mma ----------------
__global__ __launch_bounds__(256) void k_aggp() {
    __shared__ __half Ps[64][72];
    __shared__ __half Ls[64][136];
    int b = blockIdx.y, chunk = blockIdx.x;
    int n0 = chunk * 256;
    int tid = threadIdx.x;
    int warpid = tid >> 5, lane = tid & 31;
    int g = lane >> 2, l4 = lane & 3;
    int wm = (warpid >> 1) * 16;
    int wn = (warpid & 1) * 64;

    float acc[8][4];
    #pragma unroll
    for (int j = 0; j < 8; j++)
        #pragma unroll
        for (int r = 0; r < 4; r++) acc[j][r] = 0.f;

    for (int sc = 0; sc < 4; sc++) {
        int nb0 = n0 + sc * 64;
        #pragma unroll
        for (int it = 0; it < 4; it++) {
            int idx = it * 256 + tid;
            int kk = idx >> 4, nq = (idx & 15) * 4;
            float euk = g_eu[b * 65 + kk] * 8256.f;
            float4 e4 = *(const float4*)&g_E[((size_t)b * 65 + kk) * NN + nb0 + nq];
            float4 v4 = *(const float4*)&g_ev[b * NN + nb0 + nq];
            *(__half2*)&Ps[kk][nq]     = __floats2half2_rn(e4.x * v4.x * euk, e4.y * v4.y * euk);
            *(__half2*)&Ps[kk][nq + 2] = __floats2half2_rn(e4.z * v4.z * euk, e4.w * v4.w * euk);
        }
        #pragma unroll
        for (int it = 0; it < 4; it++) {
            int idx = it * 256 + tid;
            int nn = idx >> 4, dc = idx & 15;
            uint4 v = *(const uint4*)&g_localh[((size_t)b * NN + nb0 + nn) * DD + dc * 8];
            *(uint4*)&Ls[nn][dc * 8] = v;
        }
        __syncthreads();

        const uint32_t* Pu = (const uint32_t*)Ps;
        #pragma unroll
        for (int k16 = 0; k16 < 4; k16++) {
            uint32_t a[4];
            int k0 = k16 * 8;
            a[0] = Pu[(wm + g) * 36 + k0 + l4];
            a[1] = Pu[(wm + 8 + g) * 36 + k0 + l4];
            a[2] = Pu[(wm + g) * 36 + k0 + l4 + 4];
            a[3] = Pu[(wm + 8 + g) * 36 + k0 + l4 + 4];
            uint32_t baddr = smem_u32(&Ls[k16 * 16 + (lane & 15)][wn]);
            #pragma unroll
            for (int j = 0; j < 8; j++) {
                uint32_t bf[2];
                ldsm_x2_trans(bf[0], bf[1], baddr + j * 16);
                mma_f16(acc[j], a, bf);
            }
        }
        __syncthreads();
    }

    float* out = &g_aggp[((size_t)(b * 32 + chunk)) * DD * KK];
    #pragma unroll
    for (int j = 0; j < 8; j++) {
        int col = wn + j * 8 + l4 * 2;
        int r0 = wm + g;
        out[r0 * DD + col] = acc[j][0];
        out[r0 * DD + col + 1] = acc[j][1];
        out[(r0 + 8) * DD + col] = acc[j][2];
        out[(r0 + 8) * DD + col + 1] = acc[j][3];
    }
}

// ---------------- final: partial reduce + normalization ----------------
__global__ void k_final(float* __restrict__ out) {
    int b = blockIdx.x, tid = threadIdx.x;
    __shared__ float red[256];
    float gtv = g_gt[b * TOKN + tid];
    red[tid] = gtv * gtv;
    __syncthreads();
    for (int s = 128; s > 0; s >>= 1) { if (tid < s) red[tid] += red[tid + s]; __syncthreads(); }
    float S1 = red[0];
    __syncthreads();
    float s2 = 0.f;
    for (int j = tid; j < DD * KK; j += 256) {
        float s = 0.f;
        #pragma unroll
        for (int c = 0; c < 32; c++) s += g_aggp[((size_t)(b * 32 + c)) * DD * KK + j];
        g_agg[b * DD * KK + j] = s;
        s2 += s * s;
    }
    red[tid] = s2;
    __syncthreads();
    for (int s = 128; s > 0; s >>= 1) { if (tid < s) red[tid] += red[tid + s]; __syncthreads(); }
    float S2 = red[0];
    float n1 = fmaxf(sqrtf(S1), 1e-12f);
    float n2 = fmaxf(sqrtf(S2), 1e-12f);
    float tot = fmaxf(sqrtf(S1 / (n1 * n1) + S2 / (n2 * n2)), 1e-12f);
    out[(size_t)b * OUTW + tid] = (gtv / n1) / tot;
    for (int j = tid; j < DD * KK; j += 256) {
        int k = j >> 7, d = j & 127;
        out[(size_t)b * OUTW + TOKN + d * KK + k] = (g_agg[b * DD * KK + j] / n2) / tot;
    }
}

// ---------------- launcher ----------------
extern "C" void kernel_launch(void* const* d_in, const int* in_sizes, int n_in,
                              void* d_out, int out_size) {
    const float* x     = (const float*)d_in[0];
    const float* gem_w = (const float*)d_in[1];
    const float* dust  = (const float*)d_in[2];
    const float* tW1 = (const float*)d_in[3];  const float* tb1 = (const float*)d_in[4];
    const float* tW2 = (const float*)d_in[5];  const float* tb2 = (const float*)d_in[6];
    const float* cW1 = (const float*)d_in[7];  const float* cb1 = (const float*)d_in[8];
    const float* cW2 = (const float*)d_in[9];  const float* cb2 = (const float*)d_in[10];
    const float* sW1 = (const float*)d_in[11]; const float* sb1 = (const float*)d_in[12];
    const float* sW2 = (const float*)d_in[13]; const float* sb2 = (const float*)d_in[14];
    float* out = (float*)d_out;

    const int SM1 = 4 * 256 * 40 * 2;   // 81920 B (BN=128)
    const int SM2 = 4 * 192 * 40 * 2;   // 61440 B (BN=64)
    cudaFuncSetAttribute(k_mm<128, 0>, cudaFuncAttributeMaxDynamicSharedMemorySize, SM1);
    cudaFuncSetAttribute(k_mm<128, 1>, cudaFuncAttributeMaxDynamicSharedMemorySize, SM1);
    cudaFuncSetAttribute(k_mm<64, 2>,  cudaFuncAttributeMaxDynamicSharedMemorySize, SM2);

    // 4th launch (index 3) is GEMM1 -> profiled by ncu
    k_prep<<<2432, 256>>>(cW1, cb1, sW1, sb1, cW2, cb2, sW2, sb2, dust);  // 0
    k_gem_part<<<dim3(32, 8), 512>>>(x, gem_w);                          // 1
    k_head<<<8, 512>>>(gem_w, tW1, tb1, tW2, tb2);                       // 2
    k_mm<128, 0><<<dim3(8, 512), 256, SM1>>>();                          // 3 <- profiled
    k_mm<128, 1><<<dim3(1, 512), 256, SM1>>>();                          // 4 local
    k_mm<64, 2><<<dim3(1, 512), 256, SM2>>>();                           // 5 E

    for (int it = 0; it < 3; it++) {
        k_row<<<dim3(65, 8), 256>>>();
        k_col<<<dim3(32, 8), 256>>>();
    }

    k_aggp<<<dim3(32, 8), 256>>>();
    k_final<<<8, 256>>>(out);
}

// round 11
// speedup vs baseline: 1.2105x; 1.2105x over previous
#include <cuda_runtime.h>
#include <cuda_fp16.h>
#include <math.h>
#include <stdint.h>

// ---------------- problem constants ----------------
#define BB 8
#define NN 8192
#define CC 512
#define KK 64
#define DD 128
#define TOKN 256
#define MTOT (BB*NN)          // 65536
#define HDIM 1024
#define OUTW (TOKN + DD*KK)   // 8448

// ---------------- scratch (device globals) ----------------
__device__ __half g_Xh[(size_t)MTOT * CC];          // fp16 copy of x
__device__ __half g_Hh[(size_t)MTOT * HDIM];        // layer-1 activations (fp16)
__device__ float g_local[(size_t)MTOT * DD];        // local features (fp32)
__device__ float g_E[(size_t)BB * 65 * NN];         // exp(scores) [b,65,n]
__device__ float g_eu[BB * 65];
__device__ float g_ev[BB * NN];
__device__ float g_gp[BB * 32 * CC];
__device__ float g_g[BB * CC];
__device__ float g_h1[BB * 512];
__device__ float g_gt[BB * TOKN];
__device__ float g_aggp[(size_t)BB * 32 * DD * KK];
__device__ float g_agg[BB * DD * KK];
__device__ __half g_W1h[1024 * 512];                // [cW1;sW1] fp16
__device__ __half g_W2h[192 * 512];                 // [cW2;sW2] fp16
__device__ float g_b1r[1024];
__device__ float g_b2r[192];

// ---------------- helpers ----------------
__device__ __forceinline__ float compute_p(float w) {
    float sp = (w > 20.f) ? w : log1pf(expf(w));
    return fminf(sp + 1e-3f, 10.0f);
}
__device__ __forceinline__ uint32_t smem_u32(const void* p) {
    uint32_t a;
    asm("{ .reg .u64 t; cvta.to.shared.u64 t, %1; cvt.u32.u64 %0, t; }" : "=r"(a) : "l"(p));
    return a;
}
__device__ __forceinline__ void cp16(uint32_t dst, const void* src) {
    asm volatile("cp.async.cg.shared.global [%0], [%1], 16;" :: "r"(dst), "l"(src));
}
__device__ __forceinline__ void cp_commit() {
    asm volatile("cp.async.commit_group;" ::: "memory");
}
template<int N> __device__ __forceinline__ void cp_wait() {
    asm volatile("cp.async.wait_group %0;" :: "n"(N) : "memory");
}
__device__ __forceinline__ void mma_f16(float* d, const uint32_t* a, const uint32_t* b) {
    asm volatile(
        "mma.sync.aligned.m16n8k16.row.col.f32.f16.f16.f32 "
        "{%0,%1,%2,%3}, {%4,%5,%6,%7}, {%8,%9}, {%0,%1,%2,%3};\n"
        : "+f"(d[0]), "+f"(d[1]), "+f"(d[2]), "+f"(d[3])
        : "r"(a[0]), "r"(a[1]), "r"(a[2]), "r"(a[3]), "r"(b[0]), "r"(b[1]));
}
__device__ __forceinline__ void ldsm_x4(uint32_t& r0, uint32_t& r1, uint32_t& r2, uint32_t& r3,
                                        uint32_t addr) {
    asm volatile("ldmatrix.sync.aligned.m8n8.x4.shared.b16 {%0,%1,%2,%3}, [%4];"
                 : "=r"(r0), "=r"(r1), "=r"(r2), "=r"(r3) : "r"(addr));
}

// ---------------- prep: weights -> fp16 concat, ev=1, dust row of E ----------------
__global__ void k_prep(const float* __restrict__ cW1, const float* __restrict__ cb1,
                       const float* __restrict__ sW1, const float* __restrict__ sb1,
                       const float* __restrict__ cW2, const float* __restrict__ cb2,
                       const float* __restrict__ sW2, const float* __restrict__ sb2,
                       const float* __restrict__ dust) {
    int i = blockIdx.x * 256 + threadIdx.x;   // 2432*256 = 622592
    if (i < 1024 * 512) {
        g_W1h[i] = __float2half_rn(i < 512 * 512 ? cW1[i] : sW1[i - 512 * 512]);
    } else {
        int j = i - 1024 * 512;               // < 98304
        if (j < 128 * 512) g_W2h[j] = __float2half_rn(cW2[j]);
        else               g_W2h[j] = __float2half_rn(sW2[j - 128 * 512]);
    }
    if (i < 1024) g_b1r[i] = (i < 512) ? cb1[i] : sb1[i - 512];
    else if (i < 1024 + 192) { int j = i - 1024; g_b2r[j] = (j < 128) ? cb2[j] : sb2[j - 128]; }
    if (i < 65536) {
        g_ev[i] = 1.f;
        int b = i >> 13, n = i & (NN - 1);
        g_E[((size_t)b * 65 + 64) * NN + n] = expf(dust[0]);
    }
}

// ---------------- GeM pooling (+ fp16 conversion of x, fused) ----------------
__global__ void k_gem_part(const float* __restrict__ x, const float* __restrict__ gem_w) {
    int b = blockIdx.y, part = blockIdx.x, c = threadIdx.x;
    float p = compute_p(gem_w[0]);
    bool cube = fabsf(p - 3.0f) < 1e-5f;
    size_t base = ((size_t)b * NN + part * 256) * CC + c;
    const float* xp = x + base;
    __half* xh = g_Xh + base;
    float s = 0.f;
    if (cube) {
        #pragma unroll 4
        for (int n = 0; n < 256; n++) {
            float xv = xp[(size_t)n * CC];
            xh[(size_t)n * CC] = __float2half_rn(xv);
            float v = fmaxf(xv, 1e-6f);
            s += v * v * v;
        }
    } else {
        for (int n = 0; n < 256; n++) {
            float xv = xp[(size_t)n * CC];
            xh[(size_t)n * CC] = __float2half_rn(xv);
            float v = fmaxf(xv, 1e-6f);
            s += __powf(v, p);
        }
    }
    g_gp[(b * 32 + part) * CC + c] = s;
}

__global__ void k_gem_fin(const float* __restrict__ gem_w) {
    int b = blockIdx.x, c = threadIdx.x;
    float s = 0.f;
    #pragma unroll
    for (int i = 0; i < 32; i++) s += g_gp[(b * 32 + i) * CC + c];
    float p = compute_p(gem_w[0]);
    float mean = s * (1.0f / (float)NN);
    float g = powf(mean, 1.0f / p);
    if (!isfinite(g)) g = 0.f;
    g_g[b * CC + c] = g;
}

// ---------------- token MLP: warp per output ----------------
__global__ void k_tok1(const float* __restrict__ tW1, const float* __restrict__ tb1) {
    int warp = blockIdx.x * 8 + (threadIdx.x >> 5);
    int lane = threadIdx.x & 31;
    int b = warp >> 9, t = warp & 511;
    const float* g = &g_g[b * CC];
    const float* w = tW1 + (size_t)t * CC;
    float s = 0.f;
    #pragma unroll
    for (int c = lane; c < CC; c += 32) s = fmaf(g[c], w[c], s);
    #pragma unroll
    for (int o = 16; o > 0; o >>= 1) s += __shfl_xor_sync(0xffffffffu, s, o);
    if (lane == 0) g_h1[b * 512 + t] = fmaxf(s + tb1[t], 0.f);
}

__global__ void k_tok2(const float* __restrict__ tW2, const float* __restrict__ tb2) {
    int warp = blockIdx.x * 8 + (threadIdx.x >> 5);
    int lane = threadIdx.x & 31;
    int b = warp >> 8, t = warp & 255;
    const float* h = &g_h1[b * 512];
    const float* w = tW2 + (size_t)t * 512;
    float s = 0.f;
    #pragma unroll
    for (int c = lane; c < 512; c += 32) s = fmaf(h[c], w[c], s);
    #pragma unroll
    for (int o = 16; o > 0; o >>= 1) s += __shfl_xor_sync(0xffffffffu, s, o);
    if (lane == 0) g_gt[b * TOKN + t] = s + tb2[t];
}

// ================ fp16 mma.sync GEMM: BK=64, 2 stages, ldmatrix fragments ================
// BM=128, BN template, 256 threads, 2 CTAs/SM. Row stride 176 B -> conflict-free ldmatrix.
// MODE 0: Hh = relu(Xh @ W1h^T + b1)          (BN=128)
// MODE 1: local = Hh[:, :512] @ cW2h^T + b    (BN=128, fp32 store)
// MODE 2: E = exp(Hh[:, 512:] @ sW2h^T + b)   (BN=64, transposed store)
template<int BN, int MODE>
__global__ __launch_bounds__(256, 2) void k_mm() {
    constexpr int NKB = 8;                     // 512 / 64
    constexpr int ROWS = 128 + BN;
    constexpr int STRIDE_H = 88;               // 64 data halfs + 24 pad (176 B)
    constexpr int NWN = BN / 32;
    constexpr int NWM = 8 / NWN;
    constexpr int MI = (128 / NWM) / 16;

    extern __shared__ __align__(16) __half smem[];
    uint32_t sbase = smem_u32(smem);

    int tid = threadIdx.x;
    int warpid = tid >> 5, lane = tid & 31;
    int g = lane >> 2, l4 = lane & 3;
    int wm = (warpid / NWN) * (128 / NWM);
    int wn = (warpid % NWN) * 32;
    int m0 = blockIdx.y * 128;
    int col0 = blockIdx.x * BN;

    const __half* Ap; int lda; const __half* Bw; const float* bias;
    if (MODE == 0)      { Ap = g_Xh;        lda = 512;  Bw = g_W1h;             bias = g_b1r; }
    else if (MODE == 1) { Ap = g_Hh;        lda = 1024; Bw = g_W2h;             bias = g_b2r; }
    else                { Ap = g_Hh + 512;  lda = 1024; Bw = g_W2h + 128 * 512; bias = g_b2r + 128; }

    float acc[MI][4][4];
    #pragma unroll
    for (int i = 0; i < MI; i++)
        #pragma unroll
        for (int j = 0; j < 4; j++)
            #pragma unroll
            for (int r = 0; r < 4; r++) acc[i][j][r] = 0.f;

    // per-lane ldmatrix byte offsets within a stage
    int lrowA = (lane & 7) + ((lane >> 3) & 1) * 8;
    int lcol = (lane >> 4) * 8;                // halfs
    uint32_t offA[MI];
    #pragma unroll
    for (int i = 0; i < MI; i++)
        offA[i] = (uint32_t)((wm + i * 16 + lrowA) * STRIDE_H + lcol) * 2;
    uint32_t offB[2];
    #pragma unroll
    for (int jp = 0; jp < 2; jp++)
        offB[jp] = (uint32_t)((128 + wn + jp * 16 + (lane & 15)) * STRIDE_H + lcol) * 2;

    // ---- stage loader: 64 K-halfs [kb*64, kb*64+64) ----
    auto load_stage = [&](int kb, int st) {
        uint32_t base = sbase + (uint32_t)st * ROWS * STRIDE_H * 2;
        int ko = kb * 64;
        constexpr int CHUNKS = ROWS * 8;       // 16B chunks per stage
        #pragma unroll
        for (int t = 0; t < CHUNKS / 256; t++) {
            int c = tid + t * 256;
            int row = c >> 3, q = c & 7;
            const __half* src = (row < 128)
                ? (Ap + (size_t)(m0 + row) * lda + ko + q * 8)
                : (Bw + (size_t)(col0 + row - 128) * 512 + ko + q * 8);
            cp16(base + (uint32_t)(row * STRIDE_H + q * 8) * 2, src);
        }
    };

    load_stage(0, 0);
    cp_commit();

    for (int kb = 0; kb < NKB; kb++) {
        cp_wait<0>();
        __syncthreads();
        if (kb + 1 < NKB) { load_stage(kb + 1, (kb + 1) & 1); cp_commit(); }

        uint32_t stageB = sbase + (uint32_t)(kb & 1) * ROWS * STRIDE_H * 2;
        #pragma unroll
        for (int kk = 0; kk < 4; kk++) {
            uint32_t kboff = stageB + kk * 32;          // 16 halfs = 32 B
            uint32_t a[MI][4], b[4][2];
            #pragma unroll
            for (int i = 0; i < MI; i++)
                ldsm_x4(a[i][0], a[i][1], a[i][2], a[i][3], kboff + offA[i]);
            #pragma unroll
            for (int jp = 0; jp < 2; jp++)
                ldsm_x4(b[2 * jp][0], b[2 * jp + 1][0], b[2 * jp][1], b[2 * jp + 1][1],
                        kboff + offB[jp]);
            #pragma unroll
            for (int i = 0; i < MI; i++)
                #pragma unroll
                for (int j = 0; j < 4; j++)
                    mma_f16(acc[i][j], a[i], b[j]);
        }
        __syncthreads();   // all reads of this stage done before it is overwritten next round
    }

    // ---- epilogue ----
    #pragma unroll
    for (int i = 0; i < MI; i++) {
        #pragma unroll
        for (int j = 0; j < 4; j++) {
            int col = wn + j * 8 + l4 * 2;
            float b0 = bias[col0 + col], b1 = bias[col0 + col + 1];
            int r0 = m0 + wm + i * 16 + g;
            if (MODE == 0) {
                __half2 v0 = __floats2half2_rn(fmaxf(acc[i][j][0] + b0, 0.f),
                                               fmaxf(acc[i][j][1] + b1, 0.f));
                __half2 v1 = __floats2half2_rn(fmaxf(acc[i][j][2] + b0, 0.f),
                                               fmaxf(acc[i][j][3] + b1, 0.f));
                *(__half2*)&g_Hh[(size_t)r0 * HDIM + col0 + col] = v0;
                *(__half2*)&g_Hh[(size_t)(r0 + 8) * HDIM + col0 + col] = v1;
            } else if (MODE == 1) {
                size_t base0 = (size_t)r0 * DD + col0 + col;
                size_t base1 = (size_t)(r0 + 8) * DD + col0 + col;
                g_local[base0 + 0] = acc[i][j][0] + b0;
                g_local[base0 + 1] = acc[i][j][1] + b1;
                g_local[base1 + 0] = acc[i][j][2] + b0;
                g_local[base1 + 1] = acc[i][j][3] + b1;
            } else {
                int b0i = r0 >> 13, n0i = r0 & (NN - 1);
                int b1i = (r0 + 8) >> 13, n1i = (r0 + 8) & (NN - 1);
                int kc = col0 + col;
                g_E[((size_t)b0i * 65 + kc + 0) * NN + n0i] = expf(acc[i][j][0] + b0);
                g_E[((size_t)b0i * 65 + kc + 1) * NN + n0i] = expf(acc[i][j][1] + b1);
                g_E[((size_t)b1i * 65 + kc + 0) * NN + n1i] = expf(acc[i][j][2] + b0);
                g_E[((size_t)b1i * 65 + kc + 1) * NN + n1i] = expf(acc[i][j][3] + b1);
            }
        }
    }
}

// ---------------- linear-domain Sinkhorn ----------------
__global__ void k_row() {                      // grid (65, 8), 256 thr
    int m = blockIdx.x, b = blockIdx.y, tid = threadIdx.x;
    const float* row = &g_E[((size_t)b * 65 + m) * NN];
    const float* ev = &g_ev[b * NN];
    float s = 0.f;
    for (int n = tid; n < NN; n += 256) s = fmaf(row[n], ev[n], s);
    __shared__ float red[256];
    red[tid] = s;
    __syncthreads();
    #pragma unroll
    for (int o = 128; o > 0; o >>= 1) {
        if (tid < o) red[tid] += red[tid + o];
        __syncthreads();
    }
    if (tid == 0) {
        float a = (m == 64) ? (8128.f / 8256.f) : (1.f / 8256.f);
        g_eu[b * 65 + m] = a / red[0];
    }
}

__global__ void k_col() {                      // grid (32, 8), 256 thr
    int b = blockIdx.y;
    int n = blockIdx.x * 256 + threadIdx.x;
    __shared__ float us[65];
    if (threadIdx.x < 65) us[threadIdx.x] = g_eu[b * 65 + threadIdx.x];
    __syncthreads();
    const float* col = &g_E[(size_t)b * 65 * NN + n];
    float s = 0.f;
    #pragma unroll
    for (int m = 0; m < 65; m++) s = fmaf(col[(size_t)m * NN], us[m], s);
    g_ev[b * NN + n] = (1.f / 8256.f) / s;
}

// ---------------- aggregation: agg[b,d,k] = sum_n local[b,n,d]*P[b,k,n] ----------------
// P folded on the fly: P = E * eu[k] * ev[n] * 8256
__global__ __launch_bounds__(256) void k_aggp() {
    int b = blockIdx.y, chunk = blockIdx.x;
    int n0 = chunk * 256;
    int tid = threadIdx.x;
    int tx = tid & 15, ty = tid >> 4;
    int k0 = tx * 4, d0 = ty * 8;
    __shared__ float Ls[32][132];
    __shared__ float Ps[32][68];
    float acc[8][4];
    #pragma unroll
    for (int i = 0; i < 8; i++)
        #pragma unroll
        for (int j = 0; j < 4; j++) acc[i][j] = 0.f;

    for (int c = 0; c < 8; c++) {
        #pragma unroll
        for (int t = 0; t < 4; t++) {
            int f = tid + t * 256;
            int nn = f >> 5; int dq = (f & 31) * 4;
            float4 a = *reinterpret_cast<const float4*>(
                &g_local[((size_t)b * NN + n0 + c * 32 + nn) * DD + dq]);
            Ls[nn][dq + 0] = a.x; Ls[nn][dq + 1] = a.y; Ls[nn][dq + 2] = a.z; Ls[nn][dq + 3] = a.w;
        }
        #pragma unroll
        for (int t = 0; t < 2; t++) {
            int f = tid + t * 256;
            int kk = f >> 3; int nq = (f & 7) * 4;
            int nb = n0 + c * 32 + nq;
            float euk = g_eu[b * 65 + kk] * 8256.f;
            float4 e4 = *reinterpret_cast<const float4*>(&g_E[((size_t)b * 65 + kk) * NN + nb]);
            float4 v4 = *reinterpret_cast<const float4*>(&g_ev[b * NN + nb]);
            Ps[nq + 0][kk] = e4.x * v4.x * euk;
            Ps[nq + 1][kk] = e4.y * v4.y * euk;
            Ps[nq + 2][kk] = e4.z * v4.z * euk;
            Ps[nq + 3][kk] = e4.w * v4.w * euk;
        }
        __syncthreads();
        #pragma unroll
        for (int nn = 0; nn < 32; nn++) {
            float a[8], p[4];
            #pragma unroll
            for (int i = 0; i < 8; i++) a[i] = Ls[nn][d0 + i];
            #pragma unroll
            for (int j = 0; j < 4; j++) p[j] = Ps[nn][k0 + j];
            #pragma unroll
            for (int i = 0; i < 8; i++)
                #pragma unroll
                for (int j = 0; j < 4; j++) acc[i][j] = fmaf(a[i], p[j], acc[i][j]);
        }
        __syncthreads();
    }
    float* out = &g_aggp[((size_t)(b * 32 + chunk)) * DD * KK];
    #pragma unroll
    for (int i = 0; i < 8; i++)
        #pragma unroll
        for (int j = 0; j < 4; j++)
            out[(d0 + i) * KK + k0 + j] = acc[i][j];
}

__global__ void k_aggred() {
    int i = blockIdx.x * 256 + threadIdx.x;
    int b = i >> 13, r = i & 8191;
    float s = 0.f;
    #pragma unroll
    for (int c = 0; c < 32; c++) s += g_aggp[((size_t)(b * 32 + c)) * DD * KK + r];
    g_agg[i] = s;
}

// ---------------- final normalization ----------------
__global__ void k_final(float* __restrict__ out) {
    int b = blockIdx.x, tid = threadIdx.x;
    __shared__ float red[256];
    float gtv = g_gt[b * TOKN + tid];
    red[tid] = gtv * gtv;
    __syncthreads();
    for (int s = 128; s > 0; s >>= 1) { if (tid < s) red[tid] += red[tid + s]; __syncthreads(); }
    float S1 = red[0];
    __syncthreads();
    float s2 = 0.f;
    for (int i = tid; i < DD * KK; i += 256) { float v = g_agg[b * DD * KK + i]; s2 += v * v; }
    red[tid] = s2;
    __syncthreads();
    for (int s = 128; s > 0; s >>= 1) { if (tid < s) red[tid] += red[tid + s]; __syncthreads(); }
    float S2 = red[0];
    float n1 = fmaxf(sqrtf(S1), 1e-12f);
    float n2 = fmaxf(sqrtf(S2), 1e-12f);
    float tot = fmaxf(sqrtf(S1 / (n1 * n1) + S2 / (n2 * n2)), 1e-12f);
    out[(size_t)b * OUTW + tid] = (gtv / n1) / tot;
    for (int i = tid; i < DD * KK; i += 256)
        out[(size_t)b * OUTW + TOKN + i] = (g_agg[b * DD * KK + i] / n2) / tot;
}

// ---------------- launcher ----------------
extern "C" void kernel_launch(void* const* d_in, const int* in_sizes, int n_in,
                              void* d_out, int out_size) {
    const float* x     = (const float*)d_in[0];
    const float* gem_w = (const float*)d_in[1];
    const float* dust  = (const float*)d_in[2];
    const float* tW1 = (const float*)d_in[3];  const float* tb1 = (const float*)d_in[4];
    const float* tW2 = (const float*)d_in[5];  const float* tb2 = (const float*)d_in[6];
    const float* cW1 = (const float*)d_in[7];  const float* cb1 = (const float*)d_in[8];
    const float* cW2 = (const float*)d_in[9];  const float* cb2 = (const float*)d_in[10];
    const float* sW1 = (const float*)d_in[11]; const float* sb1 = (const float*)d_in[12];
    const float* sW2 = (const float*)d_in[13]; const float* sb2 = (const float*)d_in[14];
    float* out = (float*)d_out;

    const int SM1 = 2 * 256 * 88 * 2;   // 90112 B (BN=128)
    const int SM2 = 2 * 192 * 88 * 2;   // 67584 B (BN=64)
    cudaFuncSetAttribute(k_mm<128, 0>, cudaFuncAttributeMaxDynamicSharedMemorySize, SM1);
    cudaFuncSetAttribute(k_mm<128, 1>, cudaFuncAttributeMaxDynamicSharedMemorySize, SM1);
    cudaFuncSetAttribute(k_mm<64, 2>,  cudaFuncAttributeMaxDynamicSharedMemorySize, SM2);

    // launch 3 = GEMM1 -> profiled by ncu
    k_prep<<<2432, 256>>>(cW1, cb1, sW1, sb1, cW2, cb2, sW2, sb2, dust);  // 0
    k_gem_part<<<dim3(32, 8), 512>>>(x, gem_w);                          // 1
    k_gem_fin<<<8, 512>>>(gem_w);                                        // 2
    k_mm<128, 0><<<dim3(8, 512), 256, SM1>>>();                          // 3 <- profiled
    k_mm<128, 1><<<dim3(1, 512), 256, SM1>>>();                          // 4 local
    k_mm<64, 2><<<dim3(1, 512), 256, SM2>>>();                           // 5 E
    k_tok1<<<512, 256>>>(tW1, tb1);                                      // 6
    k_tok2<<<256, 256>>>(tW2, tb2);                                      // 7

    for (int it = 0; it < 3; it++) {
        k_row<<<dim3(65, 8), 256>>>();
        k_col<<<dim3(32, 8), 256>>>();
    }

    k_aggp<<<dim3(32, 8), 256>>>();
    k_aggred<<<256, 256>>>();
    k_final<<<8, 256>>>(out);
}